// round 16
// baseline (speedup 1.0000x reference)
#include <cuda_runtime.h>

#define BB   2
#define NN   8192
#define RR   2048
#define KK   16
#define CIN  64
#define CL   16
#define CFEAT 80
#define K2   256
#define COUT 128
#define NG   (BB*RR)
#define OUT_OFF (NG*3)
#define NGPB 4                 // groups per block in group_kernel (occ 4)
#define KBPB 74                // knn blocks per batch

// scratch
__device__ int    g_nb[NG * KK];
// transposed weights: [q][col] with col lane-consecutive
__device__ float4 g_t1T[12 * K2];     // t1_w [256][48]  -> q=0..11
__device__ float4 g_t2T[64 * K2];     // t2_w [256][256] -> q=0..63
__device__ float4 g_t3T[64 * K2];     // t3_w [256][256] -> q=0..63
__device__ float4 g_wT [320 * COUT];  // conv_w [128][80][16] -> q=c*4+kq (0..319)

__device__ __forceinline__ unsigned int fkey(float f) {
    unsigned int u = __float_as_uint(f);
    return (u & 0x80000000u) ? ~u : (u | 0x80000000u);
}
__device__ __forceinline__ float unfkey_hi(unsigned int hi) {
    return (hi == 0xFFFFFFFFu) ? __int_as_float(0x7f800000)
         : ((hi & 0x80000000u) ? __uint_as_float(hi ^ 0x80000000u)
                               : __uint_as_float(~hi));
}

// ---------------------------------------------------------------------------
// Prep: transpose weight matrices for lane-coalesced access
// ---------------------------------------------------------------------------
__global__ void prep_kernel(const float* __restrict__ t1_w,
                            const float* __restrict__ t2_w,
                            const float* __restrict__ t3_w,
                            const float* __restrict__ conv_w)
{
    int tid = blockIdx.x * 256 + threadIdx.x;
    if (tid < 12 * 256) {
        int q = tid >> 8, n = tid & 255;
        g_t1T[tid] = *(const float4*)(t1_w + n * 48 + q * 4);
    } else if (tid < 3072 + 64 * 256) {
        int id = tid - 3072; int q = id >> 8, n = id & 255;
        g_t2T[id] = *(const float4*)(t2_w + n * 256 + q * 4);
    } else if (tid < 19456 + 64 * 256) {
        int id = tid - 19456; int q = id >> 8, n = id & 255;
        g_t3T[id] = *(const float4*)(t3_w + n * 256 + q * 4);
    } else if (tid < 35840 + 320 * 128) {
        int id = tid - 35840; int q = id >> 7, o = id & 127;
        g_wT[id] = *(const float4*)(conv_w + o * 1280 + q * 4);
    }
}

// ---------------------------------------------------------------------------
// Kernel 1: KNN. 148 blocks (74 per batch), 1024 threads. Warp w of block
// blk handles query w*74+blk (<2048). Scan body identical to R15.
// smem: pts4[8192] float4 = 131072 B
// ---------------------------------------------------------------------------
__global__ __launch_bounds__(1024, 1)
void knn_kernel(const float* __restrict__ points,
                const int*   __restrict__ rep_idx,
                float*       __restrict__ out_rep)
{
    extern __shared__ float4 pts4[];
    const int warp = threadIdx.x >> 5;
    const int lane = threadIdx.x & 31;
    const int bi  = (blockIdx.x >= KBPB) ? 1 : 0;
    const int blk = blockIdx.x - bi * KBPB;
    const unsigned int FULL = 0xFFFFFFFFu;

    const float* pb = points + (size_t)bi * NN * 3;
    for (int n = threadIdx.x; n < NN; n += 1024) {
        float x = pb[3 * n], y = pb[3 * n + 1], z = pb[3 * n + 2];
        float sq = __fadd_rn(__fadd_rn(__fmul_rn(x, x), __fmul_rn(y, y)), __fmul_rn(z, z));
        pts4[n] = make_float4(x, y, z, sq);
    }
    __syncthreads();

    const int r = warp * KBPB + blk;       // query within batch
    if (r >= RR) return;
    const int g = bi * RR + r;

    const int n0 = rep_idx[r];
    const float4 q = pts4[n0];
    if (lane < 3) out_rep[g * 3 + lane] = (lane == 0) ? q.x : ((lane == 1) ? q.y : q.z);

    // distributed sorted top-17: lanes 0..16 hold keys ascending; others MAX
    unsigned long long lv = 0xFFFFFFFFFFFFFFFFull;
    float thr_f = __int_as_float(0x7f800000);

    for (int j0 = 0; j0 < NN; j0 += 32) {
        int j = j0 + lane;
        float4 p = pts4[j];
        float dot = __fmaf_rn(q.z, p.z, __fmaf_rn(q.y, p.y, __fmul_rn(q.x, p.x)));
        float d2  = __fsub_rn(__fadd_rn(q.w, p.w), __fmul_rn(2.0f, dot));

        unsigned int m = __ballot_sync(FULL, d2 <= thr_f);
        if (m) {
            unsigned long long key = ((unsigned long long)fkey(d2) << 32) | (unsigned int)j;
            do {
                int src = __ffs(m) - 1;
                m &= m - 1;
                unsigned long long k = __shfl_sync(FULL, key, src);
                unsigned long long thr = __shfl_sync(FULL, lv, 16);
                if (k < thr) {
                    unsigned long long up = __shfl_up_sync(FULL, lv, 1);
                    unsigned int bm = __ballot_sync(FULL, (lane <= 16) && (lv > k));
                    int pos = __ffs(bm) - 1;
                    if (lane <= 16) {
                        if (lane == pos)      lv = k;
                        else if (lane > pos)  lv = up;
                    }
                }
            } while (m);
            unsigned long long t16 = __shfl_sync(FULL, lv, 16);
            thr_f = unfkey_hi((unsigned int)(t16 >> 32));
        }
    }

    if (lane >= 1 && lane <= 16)
        g_nb[g * KK + (lane - 1)] = (int)(lv & 0xFFFFFFFFull);
}

// ---------------------------------------------------------------------------
// Kernel 2: per-group pipeline, 4 groups / block, 256 threads, occ 4
// smem floats: feat[4][16][80] | TfT[4][80][20] | hA[4][256] | hB[4][256]
// pf aliases hB (dead before h2 writes hB)
// ---------------------------------------------------------------------------
#define S_FEAT 0
#define S_TFT  5120
#define S_HA   11520
#define S_HB   12544
#define S_TOT  13568

__global__ __launch_bounds__(256, 4)
void group_kernel(
    const float* __restrict__ points,  const float* __restrict__ features,
    const float* __restrict__ lift_w,  const float* __restrict__ lift_b,
    const float* __restrict__ bnl_g,   const float* __restrict__ bnl_b,
    const float* __restrict__ t1_b,
    const float* __restrict__ bn1_g,   const float* __restrict__ bn1_b,
    const float* __restrict__ t2_b,
    const float* __restrict__ bn2_g,   const float* __restrict__ bn2_b,
    const float* __restrict__ t3_b,
    const float* __restrict__ bn3_g,   const float* __restrict__ bn3_b,
    const float* __restrict__ conv_b,
    const int*   __restrict__ rep_idx,
    float*       __restrict__ out)
{
    extern __shared__ float s[];
    float* feat = s + S_FEAT;   // [g][j][c]  g*1280 + j*80 + c
    float* TfT  = s + S_TFT;    // [g][c][i]  g*1600 + c*20 + i
    float* hA   = s + S_HA;     // [g][256]
    float* hB   = s + S_HB;     // [g][256]
    float* pf   = hB;           // alias: pf dead before h2 writes hB

    const int t  = threadIdx.x;
    const int g0 = blockIdx.x * NGPB;
    const int b  = g0 / RR;

    // ---- gather: relative positions -> pf (64 threads)
    if (t < NGPB * KK) {
        int gg = t >> 4, k = t & 15;
        int grp = g0 + gg;
        int n0 = rep_idx[grp % RR];
        const float* qp = points + (size_t)(b * NN + n0) * 3;
        int nb = g_nb[grp * KK + k];
        const float* pp = points + (size_t)(b * NN + nb) * 3;
        pf[gg * 48 + k * 3 + 0] = pp[0] - qp[0];
        pf[gg * 48 + k * 3 + 1] = pp[1] - qp[1];
        pf[gg * 48 + k * 3 + 2] = pp[2] - qp[2];
    }
    // ---- gather: neighbor features -> feat[:, :, 16:80] (256 threads)
    {
        int gg = t >> 6, k = (t >> 2) & 15, c0 = (t & 3) * 16;
        int nb = g_nb[(g0 + gg) * KK + k];
        const float4* f4 = (const float4*)(features + (size_t)(b * NN + nb) * CIN + c0);
        float* dst = feat + gg * 1280 + k * CFEAT + CL + c0;
#pragma unroll
        for (int i = 0; i < 4; ++i) {
            float4 v = f4[i];
            dst[4 * i + 0] = v.x; dst[4 * i + 1] = v.y;
            dst[4 * i + 2] = v.z; dst[4 * i + 3] = v.w;
        }
    }
    __syncthreads();

    // ---- lift -> feat[:, :, 0:16]  (NGPB*256 = 1024 elems)
#pragma unroll
    for (int u = 0; u < NGPB; ++u) {
        int f = t + u * 256;
        int gg = f >> 8, k = (f >> 4) & 15, c = f & 15;
        const float* pr = pf + gg * 48 + k * 3;
        float v = pr[0] * lift_w[c * 3 + 0] + pr[1] * lift_w[c * 3 + 1]
                + pr[2] * lift_w[c * 3 + 2] + lift_b[c];
        v = v * bnl_g[c] + bnl_b[c];
        feat[gg * 1280 + k * CFEAT + c] = fmaxf(v, 0.0f);
    }

    // ---- h1: pf @ t1T -> hA
    {
        float4 w[12];
#pragma unroll
        for (int qi = 0; qi < 12; ++qi) w[qi] = g_t1T[qi * 256 + t];
        float acc[NGPB];
        float bias = t1_b[t];
#pragma unroll
        for (int g = 0; g < NGPB; ++g) acc[g] = bias;
#pragma unroll
        for (int qi = 0; qi < 12; ++qi) {
#pragma unroll
            for (int g = 0; g < NGPB; ++g) {
                float4 p4 = *(const float4*)(pf + g * 48 + qi * 4);
                acc[g] += p4.x * w[qi].x + p4.y * w[qi].y + p4.z * w[qi].z + p4.w * w[qi].w;
            }
        }
        float sg = bn1_g[t], sb = bn1_b[t];
        __syncthreads();
#pragma unroll
        for (int g = 0; g < NGPB; ++g) hA[g * K2 + t] = fmaxf(acc[g] * sg + sb, 0.0f);
    }
    __syncthreads();

    // ---- h2: hA @ t2T -> hB (pf dead from here)
    {
        float acc[NGPB];
        float bias = t2_b[t];
#pragma unroll
        for (int g = 0; g < NGPB; ++g) acc[g] = bias;
        for (int qc = 0; qc < 64; qc += 8) {
            float4 w[8];
#pragma unroll
            for (int u = 0; u < 8; ++u) w[u] = g_t2T[(qc + u) * 256 + t];
#pragma unroll
            for (int u = 0; u < 8; ++u) {
#pragma unroll
                for (int g = 0; g < NGPB; ++g) {
                    float4 h4 = *(const float4*)(hA + g * K2 + (qc + u) * 4);
                    acc[g] += h4.x * w[u].x + h4.y * w[u].y + h4.z * w[u].z + h4.w * w[u].w;
                }
            }
        }
        float sg = bn2_g[t], sb = bn2_b[t];
        __syncthreads();   // pf reads (h1) fully done before hB overwrite
#pragma unroll
        for (int g = 0; g < NGPB; ++g) hB[g * K2 + t] = fmaxf(acc[g] * sg + sb, 0.0f);
    }
    __syncthreads();

    // ---- h3: hB @ t3T -> T in hA
    {
        float acc[NGPB];
        float bias = t3_b[t];
#pragma unroll
        for (int g = 0; g < NGPB; ++g) acc[g] = bias;
        for (int qc = 0; qc < 64; qc += 8) {
            float4 w[8];
#pragma unroll
            for (int u = 0; u < 8; ++u) w[u] = g_t3T[(qc + u) * 256 + t];
#pragma unroll
            for (int u = 0; u < 8; ++u) {
#pragma unroll
                for (int g = 0; g < NGPB; ++g) {
                    float4 h4 = *(const float4*)(hB + g * K2 + (qc + u) * 4);
                    acc[g] += h4.x * w[u].x + h4.y * w[u].y + h4.z * w[u].z + h4.w * w[u].w;
                }
            }
        }
        float sg = bn3_g[t], sb = bn3_b[t];
#pragma unroll
        for (int g = 0; g < NGPB; ++g) hA[g * K2 + t] = acc[g] * sg + sb;
    }
    __syncthreads();

    // ---- Tf[i][c] = sum_j T[i][j] * feat[j][c] -> TfT[g][c][i]
#pragma unroll
    for (int u = 0; u < 2; ++u) {
        int f4i = t + u * 256;
        if (f4i < 320) {
            int i = f4i / 20, c4 = f4i % 20;
#pragma unroll
            for (int g = 0; g < NGPB; ++g) {
                float ax = 0.f, ay = 0.f, az = 0.f, aw = 0.f;
                const float* Trow = hA + g * K2 + i * KK;
                const float* fb   = feat + g * 1280 + c4 * 4;
#pragma unroll
                for (int j = 0; j < KK; ++j) {
                    float tr = Trow[j];
                    float4 fv = *(const float4*)(fb + j * CFEAT);
                    ax += tr * fv.x; ay += tr * fv.y; az += tr * fv.z; aw += tr * fv.w;
                }
                float* dst = TfT + g * 1600 + c4 * 80 + i;
                dst[0] = ax; dst[20] = ay; dst[40] = az; dst[60] = aw;
            }
        }
    }
    __syncthreads();

    // ---- conv: out[g][o] = sum_{c,k} Tf[g][k][c] * W[o][c][k], c split halves
    {
        int o = t & 127;
        int part = t >> 7;
        float acc[NGPB];
#pragma unroll
        for (int g = 0; g < NGPB; ++g) acc[g] = 0.0f;
        int c0 = part * 40;
        for (int c = c0; c < c0 + 40; c += 2) {
            float4 w[8];
#pragma unroll
            for (int u = 0; u < 8; ++u) w[u] = g_wT[(c * 4 + u) * COUT + o];
#pragma unroll
            for (int cc = 0; cc < 2; ++cc) {
#pragma unroll
                for (int kq = 0; kq < 4; ++kq) {
                    float4 wv = w[cc * 4 + kq];
#pragma unroll
                    for (int g = 0; g < NGPB; ++g) {
                        float4 tf = *(const float4*)(TfT + g * 1600 + (c + cc) * 20 + kq * 4);
                        acc[g] += tf.x * wv.x + tf.y * wv.y + tf.z * wv.z + tf.w * wv.w;
                    }
                }
            }
        }
        __syncthreads();   // hB-era reads done before partial writes
#pragma unroll
        for (int g = 0; g < NGPB; ++g) hB[part * (NGPB * 128) + g * 128 + o] = acc[g];
    }
    __syncthreads();

    // ---- combine partials + bias, write output (NGPB*COUT = 512)
#pragma unroll
    for (int u = 0; u < 2; ++u) {
        int f = t + u * 256;
        int g = f >> 7, o = f & 127;
        float v = hB[g * 128 + o] + hB[NGPB * 128 + g * 128 + o] + conv_b[o];
        out[OUT_OFF + (size_t)(g0 + g) * COUT + o] = v;
    }
}

// ---------------------------------------------------------------------------
extern "C" void kernel_launch(void* const* d_in, const int* in_sizes, int n_in,
                              void* d_out, int out_size)
{
    const float* points   = (const float*)d_in[0];
    const float* features = (const float*)d_in[1];
    const float* lift_w   = (const float*)d_in[2];
    const float* lift_b   = (const float*)d_in[3];
    const float* bnl_g    = (const float*)d_in[4];
    const float* bnl_b    = (const float*)d_in[5];
    const float* t1_w     = (const float*)d_in[6];
    const float* t1_b     = (const float*)d_in[7];
    const float* bn1_g    = (const float*)d_in[8];
    const float* bn1_b    = (const float*)d_in[9];
    const float* t2_w     = (const float*)d_in[10];
    const float* t2_b     = (const float*)d_in[11];
    const float* bn2_g    = (const float*)d_in[12];
    const float* bn2_b    = (const float*)d_in[13];
    const float* t3_w     = (const float*)d_in[14];
    const float* t3_b     = (const float*)d_in[15];
    const float* bn3_g    = (const float*)d_in[16];
    const float* bn3_b    = (const float*)d_in[17];
    const float* conv_w   = (const float*)d_in[18];
    const float* conv_b   = (const float*)d_in[19];
    const int*   rep_idx  = (const int*)d_in[20];
    float* out = (float*)d_out;

    const int knn_smem = NN * 16;            // 131072
    const int grp_smem = S_TOT * 4;          // 54272

    static int attr_done = 0;
    if (!attr_done) {
        cudaFuncSetAttribute(knn_kernel, cudaFuncAttributeMaxDynamicSharedMemorySize, knn_smem);
        cudaFuncSetAttribute(group_kernel, cudaFuncAttributeMaxDynamicSharedMemorySize, grp_smem);
        attr_done = 1;
    }

    knn_kernel<<<2 * KBPB, 1024, knn_smem>>>(points, rep_idx, out);

    prep_kernel<<<300, 256>>>(t1_w, t2_w, t3_w, conv_w);

    group_kernel<<<NG / NGPB, 256, grp_smem>>>(
        points, features, lift_w, lift_b, bnl_g, bnl_b,
        t1_b, bn1_g, bn1_b, t2_b, bn2_g, bn2_b,
        t3_b, bn3_g, bn3_b, conv_b, rep_idx, out);
}

// round 17
// speedup vs baseline: 1.0643x; 1.0643x over previous
#include <cuda_runtime.h>

#define BB   2
#define NN   8192
#define RR   2048
#define KK   16
#define CIN  64
#define CL   16
#define CFEAT 80
#define K2   256
#define COUT 128
#define NG   (BB*RR)
#define OUT_OFF (NG*3)
#define NGPB 8                 // groups per block in group_kernel
#define QPB  32                // queries per block in knn (1 warp each)

// scratch
__device__ int    g_nb[NG * KK];
// transposed weights: [q][col] with col lane-consecutive
__device__ float4 g_t1T[12 * K2];     // t1_w [256][48]  -> q=0..11
__device__ float4 g_t2T[64 * K2];     // t2_w [256][256] -> q=0..63
__device__ float4 g_t3T[64 * K2];     // t3_w [256][256] -> q=0..63
__device__ float4 g_wT [320 * COUT];  // conv_w [128][80][16] -> q=c*4+kq (0..319)

__device__ __forceinline__ unsigned int fkey(float f) {
    unsigned int u = __float_as_uint(f);
    return (u & 0x80000000u) ? ~u : (u | 0x80000000u);
}
__device__ __forceinline__ float unfkey_hi(unsigned int hi) {
    return (hi == 0xFFFFFFFFu) ? __int_as_float(0x7f800000)
         : ((hi & 0x80000000u) ? __uint_as_float(hi ^ 0x80000000u)
                               : __uint_as_float(~hi));
}

// packed f32x2 fma (Blackwell FFMA2 — PTX-only, ptxas never auto-fuses)
__device__ __forceinline__ unsigned long long fma2(unsigned long long a,
                                                   unsigned long long b,
                                                   unsigned long long c) {
    unsigned long long d;
    asm("fma.rn.f32x2 %0, %1, %2, %3;" : "=l"(d) : "l"(a), "l"(b), "l"(c));
    return d;
}
__device__ __forceinline__ float f2_sum(unsigned long long v) {
    unsigned int lo, hi;
    asm("mov.b64 {%0, %1}, %2;" : "=r"(lo), "=r"(hi) : "l"(v));
    return __uint_as_float(lo) + __uint_as_float(hi);
}

// ---------------------------------------------------------------------------
// Prep: transpose weight matrices for lane-coalesced access
// ---------------------------------------------------------------------------
__global__ void prep_kernel(const float* __restrict__ t1_w,
                            const float* __restrict__ t2_w,
                            const float* __restrict__ t3_w,
                            const float* __restrict__ conv_w)
{
    int tid = blockIdx.x * 256 + threadIdx.x;
    if (tid < 12 * 256) {
        int q = tid >> 8, n = tid & 255;
        g_t1T[tid] = *(const float4*)(t1_w + n * 48 + q * 4);
    } else if (tid < 3072 + 64 * 256) {
        int id = tid - 3072; int q = id >> 8, n = id & 255;
        g_t2T[id] = *(const float4*)(t2_w + n * 256 + q * 4);
    } else if (tid < 19456 + 64 * 256) {
        int id = tid - 19456; int q = id >> 8, n = id & 255;
        g_t3T[id] = *(const float4*)(t3_w + n * 256 + q * 4);
    } else if (tid < 35840 + 320 * 128) {
        int id = tid - 35840; int q = id >> 7, o = id & 127;
        g_wT[id] = *(const float4*)(conv_w + o * 1280 + q * 4);
    }
}

// ---------------------------------------------------------------------------
// Kernel 1: KNN, warp per query, 32 queries / block (EXACT R15 code, 54.4µs)
// smem: pts4[8192] float4 (x,y,z,sq) = 131072 B
// ---------------------------------------------------------------------------
__global__ __launch_bounds__(1024, 1)
void knn_kernel(const float* __restrict__ points,
                const int*   __restrict__ rep_idx,
                float*       __restrict__ out_rep)
{
    extern __shared__ float4 pts4[];
    const int warp = threadIdx.x >> 5;
    const int lane = threadIdx.x & 31;
    const int g = blockIdx.x * QPB + warp;
    const int b = g / RR;
    const int r = g % RR;
    const unsigned int FULL = 0xFFFFFFFFu;

    const float* pb = points + (size_t)b * NN * 3;
    for (int n = threadIdx.x; n < NN; n += 1024) {
        float x = pb[3 * n], y = pb[3 * n + 1], z = pb[3 * n + 2];
        float sq = __fadd_rn(__fadd_rn(__fmul_rn(x, x), __fmul_rn(y, y)), __fmul_rn(z, z));
        pts4[n] = make_float4(x, y, z, sq);
    }
    __syncthreads();

    const int n0 = rep_idx[r];
    const float4 q = pts4[n0];
    if (lane < 3) out_rep[g * 3 + lane] = (lane == 0) ? q.x : ((lane == 1) ? q.y : q.z);

    unsigned long long lv = 0xFFFFFFFFFFFFFFFFull;
    float thr_f = __int_as_float(0x7f800000);

    for (int j0 = 0; j0 < NN; j0 += 32) {
        int j = j0 + lane;
        float4 p = pts4[j];
        float dot = __fmaf_rn(q.z, p.z, __fmaf_rn(q.y, p.y, __fmul_rn(q.x, p.x)));
        float d2  = __fsub_rn(__fadd_rn(q.w, p.w), __fmul_rn(2.0f, dot));

        unsigned int m = __ballot_sync(FULL, d2 <= thr_f);
        if (m) {
            unsigned long long key = ((unsigned long long)fkey(d2) << 32) | (unsigned int)j;
            do {
                int src = __ffs(m) - 1;
                m &= m - 1;
                unsigned long long k = __shfl_sync(FULL, key, src);
                unsigned long long thr = __shfl_sync(FULL, lv, 16);
                if (k < thr) {
                    unsigned long long up = __shfl_up_sync(FULL, lv, 1);
                    unsigned int bm = __ballot_sync(FULL, (lane <= 16) && (lv > k));
                    int pos = __ffs(bm) - 1;
                    if (lane <= 16) {
                        if (lane == pos)      lv = k;
                        else if (lane > pos)  lv = up;
                    }
                }
            } while (m);
            unsigned long long t16 = __shfl_sync(FULL, lv, 16);
            thr_f = unfkey_hi((unsigned int)(t16 >> 32));
        }
    }

    if (lane >= 1 && lane <= 16)
        g_nb[g * KK + (lane - 1)] = (int)(lv & 0xFFFFFFFFull);
}

// ---------------------------------------------------------------------------
// Kernel 2: per-group pipeline, 8 groups / block, 256 threads, occ 2.
// h2/h3/conv inner products use packed fma.rn.f32x2 (half the FMA-pipe ops).
// ---------------------------------------------------------------------------
#define S_FEAT 0
#define S_TFT  10240
#define S_HA   23040
#define S_HB   25088
#define S_PF   27136
#define S_TOT  27520

__global__ __launch_bounds__(256, 2)
void group_kernel(
    const float* __restrict__ points,  const float* __restrict__ features,
    const float* __restrict__ lift_w,  const float* __restrict__ lift_b,
    const float* __restrict__ bnl_g,   const float* __restrict__ bnl_b,
    const float* __restrict__ t1_b,
    const float* __restrict__ bn1_g,   const float* __restrict__ bn1_b,
    const float* __restrict__ t2_b,
    const float* __restrict__ bn2_g,   const float* __restrict__ bn2_b,
    const float* __restrict__ t3_b,
    const float* __restrict__ bn3_g,   const float* __restrict__ bn3_b,
    const float* __restrict__ conv_b,
    const int*   __restrict__ rep_idx,
    float*       __restrict__ out)
{
    extern __shared__ float s[];
    float* feat = s + S_FEAT;   // [g][j][c]  g*1280 + j*80 + c
    float* TfT  = s + S_TFT;    // [g][c][i]  g*1600 + c*20 + i
    float* hA   = s + S_HA;     // [g][256]
    float* hB   = s + S_HB;     // [g][256]
    float* pf   = s + S_PF;     // [g][48]

    const int t  = threadIdx.x;
    const int g0 = blockIdx.x * NGPB;
    const int b  = g0 / RR;

    if (t < NGPB * KK) {
        int gg = t >> 4, k = t & 15;
        int grp = g0 + gg;
        int n0 = rep_idx[grp % RR];
        const float* qp = points + (size_t)(b * NN + n0) * 3;
        int nb = g_nb[grp * KK + k];
        const float* pp = points + (size_t)(b * NN + nb) * 3;
        pf[gg * 48 + k * 3 + 0] = pp[0] - qp[0];
        pf[gg * 48 + k * 3 + 1] = pp[1] - qp[1];
        pf[gg * 48 + k * 3 + 2] = pp[2] - qp[2];
    }
    {
        int gg = t >> 5, k = (t >> 1) & 15, c0 = (t & 1) * 32;
        int nb = g_nb[(g0 + gg) * KK + k];
        const float4* f4 = (const float4*)(features + (size_t)(b * NN + nb) * CIN + c0);
        float* dst = feat + gg * 1280 + k * CFEAT + CL + c0;
#pragma unroll
        for (int i = 0; i < 8; ++i) {
            float4 v = f4[i];
            dst[4 * i + 0] = v.x; dst[4 * i + 1] = v.y;
            dst[4 * i + 2] = v.z; dst[4 * i + 3] = v.w;
        }
    }
    __syncthreads();

#pragma unroll
    for (int u = 0; u < NGPB; ++u) {
        int f = t + u * 256;
        int gg = f >> 8, k = (f >> 4) & 15, c = f & 15;
        const float* pr = pf + gg * 48 + k * 3;
        float v = pr[0] * lift_w[c * 3 + 0] + pr[1] * lift_w[c * 3 + 1]
                + pr[2] * lift_w[c * 3 + 2] + lift_b[c];
        v = v * bnl_g[c] + bnl_b[c];
        feat[gg * 1280 + k * CFEAT + c] = fmaxf(v, 0.0f);
    }

    // ---- h1: pf @ t1T -> hA  (f32x2)
    {
        ulonglong2 w[12];
#pragma unroll
        for (int qi = 0; qi < 12; ++qi) w[qi] = *(const ulonglong2*)&g_t1T[qi * 256 + t];
        unsigned long long acc2[NGPB];
        unsigned long long bias2 = (unsigned long long)__float_as_uint(t1_b[t]);
#pragma unroll
        for (int g = 0; g < NGPB; ++g) acc2[g] = bias2;
#pragma unroll
        for (int qi = 0; qi < 12; ++qi) {
#pragma unroll
            for (int g = 0; g < NGPB; ++g) {
                ulonglong2 p4 = *(const ulonglong2*)(pf + g * 48 + qi * 4);
                acc2[g] = fma2(p4.x, w[qi].x, acc2[g]);
                acc2[g] = fma2(p4.y, w[qi].y, acc2[g]);
            }
        }
        float sg = bn1_g[t], sb = bn1_b[t];
        __syncthreads();
#pragma unroll
        for (int g = 0; g < NGPB; ++g)
            hA[g * K2 + t] = fmaxf(f2_sum(acc2[g]) * sg + sb, 0.0f);
    }
    __syncthreads();

    // ---- h2: hA @ t2T -> hB  (f32x2)
    {
        unsigned long long acc2[NGPB];
        unsigned long long bias2 = (unsigned long long)__float_as_uint(t2_b[t]);
#pragma unroll
        for (int g = 0; g < NGPB; ++g) acc2[g] = bias2;
        for (int qc = 0; qc < 64; qc += 8) {
            ulonglong2 w[8];
#pragma unroll
            for (int u = 0; u < 8; ++u) w[u] = *(const ulonglong2*)&g_t2T[(qc + u) * 256 + t];
#pragma unroll
            for (int u = 0; u < 8; ++u) {
#pragma unroll
                for (int g = 0; g < NGPB; ++g) {
                    ulonglong2 h4 = *(const ulonglong2*)(hA + g * K2 + (qc + u) * 4);
                    acc2[g] = fma2(h4.x, w[u].x, acc2[g]);
                    acc2[g] = fma2(h4.y, w[u].y, acc2[g]);
                }
            }
        }
        float sg = bn2_g[t], sb = bn2_b[t];
#pragma unroll
        for (int g = 0; g < NGPB; ++g)
            hB[g * K2 + t] = fmaxf(f2_sum(acc2[g]) * sg + sb, 0.0f);
    }
    __syncthreads();

    // ---- h3: hB @ t3T -> T in hA  (f32x2)
    {
        unsigned long long acc2[NGPB];
        unsigned long long bias2 = (unsigned long long)__float_as_uint(t3_b[t]);
#pragma unroll
        for (int g = 0; g < NGPB; ++g) acc2[g] = bias2;
        for (int qc = 0; qc < 64; qc += 8) {
            ulonglong2 w[8];
#pragma unroll
            for (int u = 0; u < 8; ++u) w[u] = *(const ulonglong2*)&g_t3T[(qc + u) * 256 + t];
#pragma unroll
            for (int u = 0; u < 8; ++u) {
#pragma unroll
                for (int g = 0; g < NGPB; ++g) {
                    ulonglong2 h4 = *(const ulonglong2*)(hB + g * K2 + (qc + u) * 4);
                    acc2[g] = fma2(h4.x, w[u].x, acc2[g]);
                    acc2[g] = fma2(h4.y, w[u].y, acc2[g]);
                }
            }
        }
        float sg = bn3_g[t], sb = bn3_b[t];
#pragma unroll
        for (int g = 0; g < NGPB; ++g) hA[g * K2 + t] = f2_sum(acc2[g]) * sg + sb;
    }
    __syncthreads();

    // ---- Tf[i][c] = sum_j T[i][j] * feat[j][c] -> TfT[g][c][i]  (f32x2 pairs)
#pragma unroll
    for (int u = 0; u < 2; ++u) {
        int f4i = t + u * 256;
        if (f4i < 320) {
            int i = f4i / 20, c4 = f4i % 20;
#pragma unroll
            for (int g = 0; g < NGPB; ++g) {
                unsigned long long axy = 0ull, azw = 0ull;
                const float* Trow = hA + g * K2 + i * KK;
                const float* fb   = feat + g * 1280 + c4 * 4;
#pragma unroll
                for (int j = 0; j < KK; ++j) {
                    float tr = Trow[j];
                    unsigned long long tr2;
                    asm("mov.b64 %0, {%1, %1};" : "=l"(tr2) : "r"(__float_as_uint(tr)));
                    ulonglong2 fv = *(const ulonglong2*)(fb + j * CFEAT);
                    axy = fma2(fv.x, tr2, axy);
                    azw = fma2(fv.y, tr2, azw);
                }
                unsigned int ax, ay, az, aw;
                asm("mov.b64 {%0, %1}, %2;" : "=r"(ax), "=r"(ay) : "l"(axy));
                asm("mov.b64 {%0, %1}, %2;" : "=r"(az), "=r"(aw) : "l"(azw));
                float* dst = TfT + g * 1600 + c4 * 80 + i;
                dst[0]  = __uint_as_float(ax); dst[20] = __uint_as_float(ay);
                dst[40] = __uint_as_float(az); dst[60] = __uint_as_float(aw);
            }
        }
    }
    __syncthreads();

    // ---- conv (f32x2): out[g][o] = sum_{c,k} Tf[g][k][c] * W[o][c][k]
    {
        int o = t & 127;
        int part = t >> 7;
        unsigned long long acc2[NGPB];
#pragma unroll
        for (int g = 0; g < NGPB; ++g) acc2[g] = 0ull;
        int c0 = part * 40;
        for (int c = c0; c < c0 + 40; c += 2) {
            ulonglong2 w[8];
#pragma unroll
            for (int u = 0; u < 8; ++u) w[u] = *(const ulonglong2*)&g_wT[(c * 4 + u) * COUT + o];
#pragma unroll
            for (int cc = 0; cc < 2; ++cc) {
#pragma unroll
                for (int kq = 0; kq < 4; ++kq) {
                    ulonglong2 wv = w[cc * 4 + kq];
#pragma unroll
                    for (int g = 0; g < NGPB; ++g) {
                        ulonglong2 tf = *(const ulonglong2*)(TfT + g * 1600 + (c + cc) * 20 + kq * 4);
                        acc2[g] = fma2(tf.x, wv.x, acc2[g]);
                        acc2[g] = fma2(tf.y, wv.y, acc2[g]);
                    }
                }
            }
        }
        __syncthreads();   // TfT reads done before hB partial writes
#pragma unroll
        for (int g = 0; g < NGPB; ++g) hB[part * 1024 + g * 128 + o] = f2_sum(acc2[g]);
    }
    __syncthreads();

#pragma unroll
    for (int u = 0; u < 4; ++u) {
        int f = t + u * 256;
        int g = f >> 7, o = f & 127;
        float v = hB[g * 128 + o] + hB[1024 + g * 128 + o] + conv_b[o];
        out[OUT_OFF + (size_t)(g0 + g) * COUT + o] = v;
    }
}

// ---------------------------------------------------------------------------
extern "C" void kernel_launch(void* const* d_in, const int* in_sizes, int n_in,
                              void* d_out, int out_size)
{
    const float* points   = (const float*)d_in[0];
    const float* features = (const float*)d_in[1];
    const float* lift_w   = (const float*)d_in[2];
    const float* lift_b   = (const float*)d_in[3];
    const float* bnl_g    = (const float*)d_in[4];
    const float* bnl_b    = (const float*)d_in[5];
    const float* t1_w     = (const float*)d_in[6];
    const float* t1_b     = (const float*)d_in[7];
    const float* bn1_g    = (const float*)d_in[8];
    const float* bn1_b    = (const float*)d_in[9];
    const float* t2_w     = (const float*)d_in[10];
    const float* t2_b     = (const float*)d_in[11];
    const float* bn2_g    = (const float*)d_in[12];
    const float* bn2_b    = (const float*)d_in[13];
    const float* t3_w     = (const float*)d_in[14];
    const float* t3_b     = (const float*)d_in[15];
    const float* bn3_g    = (const float*)d_in[16];
    const float* bn3_b    = (const float*)d_in[17];
    const float* conv_w   = (const float*)d_in[18];
    const float* conv_b   = (const float*)d_in[19];
    const int*   rep_idx  = (const int*)d_in[20];
    float* out = (float*)d_out;

    const int knn_smem = NN * 16;            // 131072
    const int grp_smem = S_TOT * 4;          // 110080

    static int attr_done = 0;
    if (!attr_done) {
        cudaFuncSetAttribute(knn_kernel, cudaFuncAttributeMaxDynamicSharedMemorySize, knn_smem);
        cudaFuncSetAttribute(group_kernel, cudaFuncAttributeMaxDynamicSharedMemorySize, grp_smem);
        attr_done = 1;
    }

    knn_kernel<<<NG / QPB, 1024, knn_smem>>>(points, rep_idx, out);

    prep_kernel<<<300, 256>>>(t1_w, t2_w, t3_w, conv_w);

    group_kernel<<<NG / NGPB, 256, grp_smem>>>(
        points, features, lift_w, lift_b, bnl_g, bnl_b,
        t1_b, bn1_g, bn1_b, t2_b, bn2_g, bn2_b,
        t3_b, bn3_g, bn3_b, conv_b, rep_idx, out);
}